// round 3
// baseline (speedup 1.0000x reference)
#include <cuda_runtime.h>

// Problem constants
#define B_      16
#define HW_     65536      // 256*256
#define HW4_    16384      // HW/4
#define HID_    64
#define TDIM_   512

// Packed parameter blocks written by precompute kernel, read by main kernel.
// g_all layout (floats):
//  [0..5]  G6: G00,G11,G22, 2*G01, 2*G02, 2*G12   (G = Wz^T Wz)
//  [6..14] M (3x3 row-major): M = out_w @ z_proj_w
//  [15..17] q = out_w @ z_proj_b
//  [18..20] out_b copy
//  [21] gamma = exp(log_gamma), [22] alpha, [23] c
//  [24..26] w0,w1,w2, [27] 1/(w0+w1+w2+1e-8)
__device__ __align__(16) float g_all[32];
// per-batch (8 floats each): [0..2]=u (Wz^T t), [3]=c0 (b.t),
//                            [4..6]=dcoef (2g-2u), [7]=dconst (|b|^2+|t|^2-2c0)
__device__ __align__(16) float g_bat[B_ * 8];

__global__ void precompute_kernel(const float* __restrict__ text_vec,
                                  const float* __restrict__ zw,   // (64,3)
                                  const float* __restrict__ zpb,  // (64)
                                  const float* __restrict__ tw,   // (64,512)
                                  const float* __restrict__ tb,   // (64)
                                  const float* __restrict__ ow,   // (3,64)
                                  const float* __restrict__ ob,   // (3)
                                  const float* __restrict__ lg,
                                  const float* __restrict__ alpha,
                                  const float* __restrict__ cc,
                                  const float* __restrict__ wv) {
    __shared__ float st[HID_];
    int b = blockIdx.x;
    int o = threadIdx.x;   // 0..63

    // t[b][o] = text_vec[b] . tw[o] + tb[o]   (K=512, float4, 2-way ILP)
    const float4* tv4 = (const float4*)(text_vec + b * TDIM_);
    const float4* twr = (const float4*)(tw + o * TDIM_);
    float accA = tb[o], accB = 0.f;
#pragma unroll 16
    for (int i = 0; i < TDIM_ / 8; i++) {
        float4 a0 = tv4[2 * i],     w0 = twr[2 * i];
        float4 a1 = tv4[2 * i + 1], w1 = twr[2 * i + 1];
        accA += a0.x * w0.x + a0.y * w0.y + a0.z * w0.z + a0.w * w0.w;
        accB += a1.x * w1.x + a1.y * w1.y + a1.z * w1.z + a1.w * w1.w;
    }
    st[o] = accA + accB;
    __syncthreads();

    // Per-batch reductions (fixed-order serial loops -> deterministic)
    if (o < 3) {
        float u = 0.f, g = 0.f;
        for (int j = 0; j < HID_; j++) {
            float zj = zw[j * 3 + o];
            u += zj * st[j];
            g += zj * zpb[j];
        }
        g_bat[b * 8 + o]     = u;
        g_bat[b * 8 + 4 + o] = 2.f * g - 2.f * u;
    } else if (o == 3) {
        float c0 = 0.f, tn2 = 0.f, zb2 = 0.f;
        for (int j = 0; j < HID_; j++) {
            c0  += zpb[j] * st[j];
            tn2 += st[j] * st[j];
            zb2 += zpb[j] * zpb[j];
        }
        g_bat[b * 8 + 3] = c0;
        g_bat[b * 8 + 7] = zb2 + tn2 - 2.f * c0;
    }

    // Global (weight-only) folded params: computed once by block 0
    if (b == 0) {
        if (o >= 8 && o < 14) {
            int k = o - 8;
            int i, j;
            switch (k) {
                case 0: i = 0; j = 0; break;
                case 1: i = 1; j = 1; break;
                case 2: i = 2; j = 2; break;
                case 3: i = 0; j = 1; break;
                case 4: i = 0; j = 2; break;
                default: i = 1; j = 2; break;
            }
            float s = 0.f;
            for (int h = 0; h < HID_; h++) s += zw[h * 3 + i] * zw[h * 3 + j];
            g_all[k] = (i == j) ? s : 2.f * s;
        } else if (o >= 16 && o < 25) {
            int k = o - 16;
            int r = k / 3, cch = k % 3;
            float s = 0.f;
            for (int h = 0; h < HID_; h++) s += ow[r * HID_ + h] * zw[h * 3 + cch];
            g_all[6 + k] = s;
        } else if (o >= 25 && o < 28) {
            int r = o - 25;
            float s = 0.f;
            for (int h = 0; h < HID_; h++) s += ow[r * HID_ + h] * zpb[h];
            g_all[15 + r] = s;
        } else if (o >= 28 && o < 31) {
            g_all[18 + (o - 28)] = ob[o - 28];
        } else if (o == 31) {
            g_all[21] = __expf(lg[0]);
            g_all[22] = alpha[0];
            g_all[23] = cc[0];
            float w0 = wv[0], w1 = wv[1], w2 = wv[2];
            g_all[24] = w0; g_all[25] = w1; g_all[26] = w2;
            g_all[27] = 1.f / (w0 + w1 + w2 + 1e-8f);
        }
    }
}

__global__ void __launch_bounds__(256)
fused_kernel(const float* __restrict__ z, float* __restrict__ out) {
    unsigned t = blockIdx.x * 256u + threadIdx.x;   // 0 .. 262143
    unsigned b = t >> 14;                           // / HW4_
    unsigned p = t & (HW4_ - 1u);

    // Front-batch the three DRAM tile loads (the only long-latency ops)
    const float4* z4 = (const float4*)z;
    float4* o4 = (float4*)out;
    unsigned base = b * (3u * HW4_) + p;            // < 786432, fits 32-bit
    float4 A  = z4[base];
    float4 Bc = z4[base + HW4_];
    float4 C  = z4[base + 2u * HW4_];

    // Per-batch params (2 x LDG.128, L2/L1-resident after first wave)
    const float4* gb = (const float4*)(g_bat + b * 8u);
    float4 U = gb[0];   // u0,u1,u2,c0
    float4 D = gb[1];   // d0,d1,d2,dconst

    // Global params (7 x LDG.128)
    const float4* ga = (const float4*)g_all;
    float4 P0 = ga[0], P1 = ga[1], P2 = ga[2], P3 = ga[3],
           P4 = ga[4], P5 = ga[5], P6 = ga[6];

    float G00 = P0.x, G11 = P0.y, G22 = P0.z, G01 = P0.w;
    float G02 = P1.x, G12 = P1.y;
    float M00 = P1.z, M01 = P1.w;
    float M02 = P2.x, M10 = P2.y, M11 = P2.z, M12 = P2.w;
    float M20 = P3.x, M21 = P3.y, M22 = P3.z;
    float q0  = P3.w, q1  = P4.x, q2  = P4.y;
    float ob0 = P4.z, ob1 = P4.w, ob2 = P5.x;
    float gamma = P5.y, alpha = P5.z, cc = P5.w;
    float w0 = P6.x, w1 = P6.y, w2 = P6.z, invw = P6.w;

    float zi0[4] = {A.x, A.y, A.z, A.w};
    float zi1[4] = {Bc.x, Bc.y, Bc.z, Bc.w};
    float zi2[4] = {C.x, C.y, C.z, C.w};
    float r0[4], r1[4], r2[4];

#pragma unroll
    for (int i = 0; i < 4; i++) {
        float z0 = zi0[i], z1 = zi1[i], z2 = zi2[i];
        // k_lin = u.z + c0
        float klin = U.x * z0 + U.y * z1 + U.z * z2 + U.w;
        // dist = z^T G z + d.z + dconst
        float quad = z0 * (G00 * z0 + G01 * z1 + G02 * z2)
                   + z1 * (G11 * z1 + G12 * z2)
                   + G22 * z2 * z2;
        float dist = quad + D.x * z0 + D.y * z1 + D.z * z2 + D.w;
        float krbf = __expf(-gamma * dist);
        float kpb  = alpha * klin + cc;
        float kpoly = kpb * kpb;
        float k = (w0 * krbf + w1 * klin + w2 * kpoly) * invw;
        float s = 1.f + __fdividef(1.f, 1.f + __expf(-k));
        r0[i] = s * (M00 * z0 + M01 * z1 + M02 * z2 + q0) + ob0;
        r1[i] = s * (M10 * z0 + M11 * z1 + M12 * z2 + q1) + ob1;
        r2[i] = s * (M20 * z0 + M21 * z1 + M22 * z2 + q2) + ob2;
    }

    o4[base]             = make_float4(r0[0], r0[1], r0[2], r0[3]);
    o4[base + HW4_]      = make_float4(r1[0], r1[1], r1[2], r1[3]);
    o4[base + 2u * HW4_] = make_float4(r2[0], r2[1], r2[2], r2[3]);
}

extern "C" void kernel_launch(void* const* d_in, const int* in_sizes, int n_in,
                              void* d_out, int out_size) {
    const float* z   = (const float*)d_in[0];
    const float* tv  = (const float*)d_in[1];
    const float* zw  = (const float*)d_in[2];
    const float* zpb = (const float*)d_in[3];
    const float* tw  = (const float*)d_in[4];
    const float* tb  = (const float*)d_in[5];
    const float* ow  = (const float*)d_in[6];
    const float* ob  = (const float*)d_in[7];
    const float* lg  = (const float*)d_in[8];
    const float* al  = (const float*)d_in[9];
    const float* cc  = (const float*)d_in[10];
    const float* wv  = (const float*)d_in[11];
    float* out = (float*)d_out;

    precompute_kernel<<<B_, HID_>>>(tv, zw, zpb, tw, tb, ow, ob, lg, al, cc, wv);
    fused_kernel<<<(B_ * HW4_) / 256, 256>>>(z, out);
}

// round 4
// speedup vs baseline: 1.0014x; 1.0014x over previous
#include <cuda_runtime.h>

// Problem constants
#define B_      16
#define HW_     65536      // 256*256
#define HW4_    16384      // float4 per channel-plane per batch
#define HID_    64
#define TDIM_   512

// g_all layout (floats) — all gamma/w prefolded:
//  [0..5]  G6g = -gamma * {G00,G11,G22, 2G01, 2G02, 2G12}   (G = Wz^T Wz)
//  [6..14] M (3x3 row-major) = out_w @ z_proj_w
//  [15..17] q = out_w @ z_proj_b
//  [18..20] out_b
//  [21] A  = w2' * alpha^2        (wi' = wi / (w0+w1+w2+1e-8))
//  [22] Bp = w1' + 2*w2'*alpha*c
//  [23] Cp = w2' * c^2
//  [24] w0p = w0'
__device__ __align__(16) float g_all[32];
// per-batch (8 floats): [0..2]=u (Wz^T t), [3]=c0 (b.t),
// [4..6]=Dg = -gamma*(2g-2u), [7]=Dgc = -gamma*(|b|^2+|t|^2-2c0)
__device__ __align__(16) float g_bat[B_ * 8];

__global__ void __launch_bounds__(256)
precompute_kernel(const float* __restrict__ text_vec,
                  const float* __restrict__ zw,   // (64,3)
                  const float* __restrict__ zpb,  // (64)
                  const float* __restrict__ tw,   // (64,512)
                  const float* __restrict__ tb,   // (64)
                  const float* __restrict__ ow,   // (3,64)
                  const float* __restrict__ ob,   // (3)
                  const float* __restrict__ lg,
                  const float* __restrict__ alpha,
                  const float* __restrict__ cc,
                  const float* __restrict__ wv) {
    __shared__ float st[HID_];
    int b   = blockIdx.x;
    int tid = threadIdx.x;          // 0..255
    int o   = tid >> 2;             // 0..63  output index
    int q   = tid & 3;              // quad lane: splits the K=512 dot 4 ways

    // t[b][o] = text_vec[b] . tw[o] + tb[o]; each thread sums 128 contiguous
    // elements (32 float4), then deterministic quad shfl-reduce.
    const float4* tv4 = (const float4*)(text_vec + b * TDIM_);
    const float4* twr = (const float4*)(tw + o * TDIM_);
    float acc = 0.f;
    int i0 = q * 32;
#pragma unroll 8
    for (int i = 0; i < 32; i++) {
        float4 a = tv4[i0 + i];
        float4 w4 = twr[i0 + i];
        acc += a.x * w4.x + a.y * w4.y + a.z * w4.z + a.w * w4.w;
    }
    acc += __shfl_xor_sync(0xffffffffu, acc, 1);
    acc += __shfl_xor_sync(0xffffffffu, acc, 2);
    if (q == 0) st[o] = acc + tb[o];
    __syncthreads();

    // Per-batch tail (fixed-order serial loops -> deterministic)
    if (tid < 3) {
        float gam = __expf(lg[0]);
        float u = 0.f, g = 0.f;
        for (int j = 0; j < HID_; j++) {
            float zj = zw[j * 3 + tid];
            u += zj * st[j];
            g += zj * zpb[j];
        }
        g_bat[b * 8 + tid]     = u;
        g_bat[b * 8 + 4 + tid] = -gam * (2.f * g - 2.f * u);
    } else if (tid == 3) {
        float gam = __expf(lg[0]);
        float c0 = 0.f, tn2 = 0.f, zb2 = 0.f;
        for (int j = 0; j < HID_; j++) {
            c0  += zpb[j] * st[j];
            tn2 += st[j] * st[j];
            zb2 += zpb[j] * zpb[j];
        }
        g_bat[b * 8 + 3] = c0;
        g_bat[b * 8 + 7] = -gam * (zb2 + tn2 - 2.f * c0);
    }

    // Global (weight-only) folded params: block 0 only
    if (b == 0) {
        if (tid >= 8 && tid < 14) {
            int k = tid - 8;
            int i, j;
            switch (k) {
                case 0: i = 0; j = 0; break;
                case 1: i = 1; j = 1; break;
                case 2: i = 2; j = 2; break;
                case 3: i = 0; j = 1; break;
                case 4: i = 0; j = 2; break;
                default: i = 1; j = 2; break;
            }
            float gam = __expf(lg[0]);
            float s = 0.f;
            for (int h = 0; h < HID_; h++) s += zw[h * 3 + i] * zw[h * 3 + j];
            g_all[k] = -gam * ((i == j) ? s : 2.f * s);
        } else if (tid >= 16 && tid < 25) {
            int k = tid - 16;
            int r = k / 3, cch = k % 3;
            float s = 0.f;
            for (int h = 0; h < HID_; h++) s += ow[r * HID_ + h] * zw[h * 3 + cch];
            g_all[6 + k] = s;
        } else if (tid >= 25 && tid < 28) {
            int r = tid - 25;
            float s = 0.f;
            for (int h = 0; h < HID_; h++) s += ow[r * HID_ + h] * zpb[h];
            g_all[15 + r] = s;
        } else if (tid >= 28 && tid < 31) {
            g_all[18 + (tid - 28)] = ob[tid - 28];
        } else if (tid == 31) {
            float al = alpha[0], c = cc[0];
            float w0 = wv[0], w1 = wv[1], w2 = wv[2];
            float invw = 1.f / (w0 + w1 + w2 + 1e-8f);
            float w1p = w1 * invw, w2p = w2 * invw;
            g_all[21] = w2p * al * al;
            g_all[22] = w1p + 2.f * w2p * al * c;
            g_all[23] = w2p * c * c;
            g_all[24] = w0 * invw;
        }
    }
}

// 8 pixels (2 float4 per channel) per thread; 6 front-batched LDG.128.
__global__ void __launch_bounds__(256)
fused_kernel(const float* __restrict__ z, float* __restrict__ out) {
    unsigned g = blockIdx.x * 256u + threadIdx.x;   // 0 .. 131071
    unsigned b = g >> 13;                           // batch (8192 threads/batch)
    unsigned r = g & 8191u;
    unsigned base = b * (3u * HW4_) + 2u * r;       // float4 units, fits 32-bit

    const float4* z4 = (const float4*)z;
    float4* o4 = (float4*)out;

    // Front-batch all 6 tile loads
    float4 A0 = z4[base],               A1 = z4[base + 1u];
    float4 B0 = z4[base + HW4_],        B1 = z4[base + HW4_ + 1u];
    float4 C0 = z4[base + 2u * HW4_],   C1 = z4[base + 2u * HW4_ + 1u];

    // Per-batch params
    const float4* gb = (const float4*)(g_bat + b * 8u);
    float4 U = gb[0];    // u0,u1,u2,c0
    float4 D = gb[1];    // Dg0,Dg1,Dg2,Dgc

    // Global params (7 x LDG.128)
    const float4* ga = (const float4*)g_all;
    float4 P0 = ga[0], P1 = ga[1], P2 = ga[2], P3 = ga[3],
           P4 = ga[4], P5 = ga[5], P6 = ga[6];

    float G00 = P0.x, G11 = P0.y, G22 = P0.z, G01 = P0.w;  // pre-scaled by -gamma
    float G02 = P1.x, G12 = P1.y;
    float M00 = P1.z, M01 = P1.w;
    float M02 = P2.x, M10 = P2.y, M11 = P2.z, M12 = P2.w;
    float M20 = P3.x, M21 = P3.y, M22 = P3.z;
    float q0  = P3.w, q1  = P4.x, q2  = P4.y;
    float ob0 = P4.z, ob1 = P4.w, ob2 = P5.x;
    float Ak  = P5.y, Bk  = P5.z, Ck  = P5.w;
    float w0p = P6.x;

    float zi0[8] = {A0.x, A0.y, A0.z, A0.w, A1.x, A1.y, A1.z, A1.w};
    float zi1[8] = {B0.x, B0.y, B0.z, B0.w, B1.x, B1.y, B1.z, B1.w};
    float zi2[8] = {C0.x, C0.y, C0.z, C0.w, C1.x, C1.y, C1.z, C1.w};
    float r0[8], r1[8], r2[8];

#pragma unroll
    for (int i = 0; i < 8; i++) {
        float z0 = zi0[i], z1 = zi1[i], z2 = zi2[i];
        float klin = U.x * z0 + U.y * z1 + U.z * z2 + U.w;
        // earg = -gamma*dist  (all coefs pre-scaled)
        float quad = z0 * (G00 * z0 + G01 * z1 + G02 * z2)
                   + z1 * (G11 * z1 + G12 * z2)
                   + G22 * z2 * z2;
        float earg = quad + D.x * z0 + D.y * z1 + D.z * z2 + D.w;
        float krbf = __expf(earg);
        float k = fmaf(w0p, krbf, fmaf(fmaf(Ak, klin, Bk), klin, Ck));
        float s = 1.f + __fdividef(1.f, 1.f + __expf(-k));
        r0[i] = s * (M00 * z0 + M01 * z1 + M02 * z2 + q0) + ob0;
        r1[i] = s * (M10 * z0 + M11 * z1 + M12 * z2 + q1) + ob1;
        r2[i] = s * (M20 * z0 + M21 * z1 + M22 * z2 + q2) + ob2;
    }

    o4[base]                = make_float4(r0[0], r0[1], r0[2], r0[3]);
    o4[base + 1u]           = make_float4(r0[4], r0[5], r0[6], r0[7]);
    o4[base + HW4_]         = make_float4(r1[0], r1[1], r1[2], r1[3]);
    o4[base + HW4_ + 1u]    = make_float4(r1[4], r1[5], r1[6], r1[7]);
    o4[base + 2u * HW4_]    = make_float4(r2[0], r2[1], r2[2], r2[3]);
    o4[base + 2u * HW4_ + 1u] = make_float4(r2[4], r2[5], r2[6], r2[7]);
}

extern "C" void kernel_launch(void* const* d_in, const int* in_sizes, int n_in,
                              void* d_out, int out_size) {
    const float* z   = (const float*)d_in[0];
    const float* tv  = (const float*)d_in[1];
    const float* zw  = (const float*)d_in[2];
    const float* zpb = (const float*)d_in[3];
    const float* tw  = (const float*)d_in[4];
    const float* tb  = (const float*)d_in[5];
    const float* ow  = (const float*)d_in[6];
    const float* ob  = (const float*)d_in[7];
    const float* lg  = (const float*)d_in[8];
    const float* al  = (const float*)d_in[9];
    const float* cc  = (const float*)d_in[10];
    const float* wv  = (const float*)d_in[11];
    float* out = (float*)d_out;

    precompute_kernel<<<B_, 256>>>(tv, zw, zpb, tw, tb, ow, ob, lg, al, cc, wv);
    fused_kernel<<<512, 256>>>(z, out);
}